// round 1
// baseline (speedup 1.0000x reference)
#include <cuda_runtime.h>
#include <math.h>

#define B_   4
#define C_   256
#define D_   128
#define HW_  16384
#define W_   128
#define T_   16384
#define NPTS 128
#define MAX_DELTA 0.0009765625f   // 0.5/512

// 32 MB scratch for projected feature map, channel-last: vm[b][pix][d]
__device__ float g_vm[(size_t)B_ * HW_ * D_];

// ---------------------------------------------------------------------------
// Kernel 1: projection GEMM  vm[b, m, d] = sum_c fmap[b, c, m] * Wp[d, c]
// Tile: 128 pixels x 128 d, K-chunks of 16, 256 threads, 8x8 microtile.
// ---------------------------------------------------------------------------
__global__ __launch_bounds__(256) void proj_kernel(const float* __restrict__ fmap,
                                                   const float* __restrict__ Wp)
{
    __shared__ __align__(16) float As[16][128];   // As[k][m]
    __shared__ __align__(16) float Bs[16][128];   // Bs[k][d]

    const int b      = blockIdx.y;
    const int m_base = blockIdx.x * 128;
    const int tid    = threadIdx.x;
    const int td = tid & 15, tm = tid >> 4;
    const int m0 = tm * 8,  d0 = td * 8;

    float acc[8][8];
#pragma unroll
    for (int i = 0; i < 8; i++)
#pragma unroll
        for (int j = 0; j < 8; j++) acc[i][j] = 0.f;

    for (int k0 = 0; k0 < C_; k0 += 16) {
        // load A tile: fmap[b][k0+k][m_base+m], coalesced over m
#pragma unroll
        for (int i = 0; i < 8; i++) {
            int k = i * 2 + (tid >> 7);
            int m = tid & 127;
            As[k][m] = fmap[((size_t)b * C_ + k0 + k) * HW_ + m_base + m];
        }
        // load B tile: Wp[d][k0+k]
#pragma unroll
        for (int i = 0; i < 8; i++) {
            int k = tid & 15;
            int d = i * 16 + (tid >> 4);
            Bs[k][d] = Wp[d * C_ + k0 + k];
        }
        __syncthreads();

#pragma unroll
        for (int kk = 0; kk < 16; kk++) {
            float4 a0 = *(const float4*)&As[kk][m0];
            float4 a1 = *(const float4*)&As[kk][m0 + 4];
            float4 c0 = *(const float4*)&Bs[kk][d0];
            float4 c1 = *(const float4*)&Bs[kk][d0 + 4];
            float a[8] = {a0.x, a0.y, a0.z, a0.w, a1.x, a1.y, a1.z, a1.w};
            float bb[8] = {c0.x, c0.y, c0.z, c0.w, c1.x, c1.y, c1.z, c1.w};
#pragma unroll
            for (int i = 0; i < 8; i++)
#pragma unroll
                for (int j = 0; j < 8; j++)
                    acc[i][j] = fmaf(a[i], bb[j], acc[i][j]);
        }
        __syncthreads();
    }

#pragma unroll
    for (int i = 0; i < 8; i++) {
        size_t base = ((size_t)b * HW_ + m_base + m0 + i) * D_ + d0;
        *(float4*)&g_vm[base]     = make_float4(acc[i][0], acc[i][1], acc[i][2], acc[i][3]);
        *(float4*)&g_vm[base + 4] = make_float4(acc[i][4], acc[i][5], acc[i][6], acc[i][7]);
    }
}

// ---------------------------------------------------------------------------
// Kernel 2: fused 4x4 separable stencil sampling + 2-layer MLP + coord update.
// Block = 256 threads, NPTS=128 points.
//   Phase 1: warp-per-point sampling (lane owns 4 channels, LDG.128 gathers)
//   Phase 2: feat(128x128) @ W1^T(128x128) with 8x8 microtiles;
//            layer 2 (W2, tanh) folded into epilogue via smem partial reduce.
// ---------------------------------------------------------------------------
__global__ __launch_bounds__(256) void sample_mlp_kernel(
    const float* __restrict__ coords, const float* __restrict__ W1,
    const float* __restrict__ b1,     const float* __restrict__ W2,
    const float* __restrict__ b2,     float* __restrict__ out)
{
    extern __shared__ float smem[];
    float* featS = smem;                       // 128*128 floats (64 KB), [pt][ch]
    float* BsW   = smem + 128 * 128;           // 16*128 floats  (8 KB),  [k][j]
    float* red   = BsW  + 16 * 128;            // 16*258 floats  (~16 KB)

    const int tid  = threadIdx.x;
    const int lane = tid & 31, warp = tid >> 5;
    const int ptBase = blockIdx.x * NPTS;

    // ---------------- Phase 1: sampling ----------------
    const float inv9 = 1.f / 9.f;
    for (int pp = 0; pp < NPTS / 8; pp++) {
        int pt  = warp * (NPTS / 8) + pp;
        int gpt = ptBase + pt;
        int b   = gpt >> 14;

        float cx = coords[2 * gpt], cy = coords[2 * gpt + 1];
        float ix = cx * 127.f, iy = cy * 127.f;
        float xf = floorf(ix), yf = floorf(iy);
        int   x0 = (int)xf,    y0 = (int)yf;
        float fx = ix - xf,    fy = iy - yf;
        // mean of 9 bilinear samples == separable 4x4 stencil:
        float Xw[4] = {1.f - fx, 1.f, 1.f, fx};
        float Yw[4] = {1.f - fy, 1.f, 1.f, fy};

        float4 acc = make_float4(0.f, 0.f, 0.f, 0.f);
        const float4* vmb = ((const float4*)g_vm) + (size_t)b * HW_ * 32 + lane;
#pragma unroll
        for (int j = 0; j < 4; j++) {
            int py = y0 - 1 + j;
            if ((unsigned)py > 127u) continue;
#pragma unroll
            for (int i = 0; i < 4; i++) {
                int px = x0 - 1 + i;
                if ((unsigned)px > 127u) continue;
                float w = Yw[j] * Xw[i];
                float4 v = vmb[(size_t)(py * W_ + px) * 32];
                acc.x = fmaf(w, v.x, acc.x);
                acc.y = fmaf(w, v.y, acc.y);
                acc.z = fmaf(w, v.z, acc.z);
                acc.w = fmaf(w, v.w, acc.w);
            }
        }
        acc.x *= inv9; acc.y *= inv9; acc.z *= inv9; acc.w *= inv9;
        ((float4*)(featS + pt * 128))[lane] = acc;
    }
    __syncthreads();

    // ---------------- Phase 2: MLP GEMM ----------------
    const int td = tid & 15, tm = tid >> 4;
    const int m0 = tm * 8,   j0 = td * 8;

    float acc[8][8];
#pragma unroll
    for (int i = 0; i < 8; i++)
#pragma unroll
        for (int j = 0; j < 8; j++) acc[i][j] = 0.f;

    for (int k0 = 0; k0 < 128; k0 += 16) {
#pragma unroll
        for (int i = 0; i < 8; i++) {
            int k = tid & 15;
            int j = i * 16 + (tid >> 4);
            BsW[k * 128 + j] = W1[j * 128 + k0 + k];
        }
        __syncthreads();
#pragma unroll
        for (int kk = 0; kk < 16; kk++) {
            float a[8];
#pragma unroll
            for (int i = 0; i < 8; i++) a[i] = featS[(m0 + i) * 128 + k0 + kk];
            float4 c0 = *(const float4*)&BsW[kk * 128 + j0];
            float4 c1 = *(const float4*)&BsW[kk * 128 + j0 + 4];
            float bb[8] = {c0.x, c0.y, c0.z, c0.w, c1.x, c1.y, c1.z, c1.w};
#pragma unroll
            for (int i = 0; i < 8; i++)
#pragma unroll
                for (int j = 0; j < 8; j++)
                    acc[i][j] = fmaf(a[i], bb[j], acc[i][j]);
        }
        __syncthreads();
    }

    // epilogue: h = relu(acc + b1); partial (W2 @ h) per thread -> smem reduce
    float b1v[8], w20[8], w21[8];
#pragma unroll
    for (int i = 0; i < 8; i++) {
        b1v[i] = b1[j0 + i];
        w20[i] = W2[j0 + i];
        w21[i] = W2[128 + j0 + i];
    }
#pragma unroll
    for (int mi = 0; mi < 8; mi++) {
        float s0 = 0.f, s1 = 0.f;
#pragma unroll
        for (int ji = 0; ji < 8; ji++) {
            float h = acc[mi][ji] + b1v[ji];
            h = fmaxf(h, 0.f);
            s0 = fmaf(w20[ji], h, s0);
            s1 = fmaf(w21[ji], h, s1);
        }
        red[td * 258 + (m0 + mi) * 2 + 0] = s0;
        red[td * 258 + (m0 + mi) * 2 + 1] = s1;
    }
    __syncthreads();

    // final reduce over the 16 j-groups + tanh + coord update
    {
        int pt = tid >> 1, c = tid & 1;
        float s = b2[c];
#pragma unroll
        for (int g = 0; g < 16; g++) s += red[g * 258 + pt * 2 + c];
        float v = tanhf(s) * MAX_DELTA;
        int gi = (ptBase + pt) * 2 + c;
        out[gi] = coords[gi] + v;
    }
}

// ---------------------------------------------------------------------------
extern "C" void kernel_launch(void* const* d_in, const int* in_sizes, int n_in,
                              void* d_out, int out_size)
{
    (void)in_sizes; (void)n_in; (void)out_size;
    const float* fmap   = (const float*)d_in[0];
    const float* coords = (const float*)d_in[1];
    const float* Wp     = (const float*)d_in[2];
    const float* W1     = (const float*)d_in[3];
    const float* b1     = (const float*)d_in[4];
    const float* W2     = (const float*)d_in[5];
    const float* b2     = (const float*)d_in[6];
    float* out = (float*)d_out;

    proj_kernel<<<dim3(HW_ / 128, B_), 256>>>(fmap, Wp);

    const int smem_bytes = (128 * 128 + 16 * 128 + 16 * 258) * 4;  // 90240 B
    cudaFuncSetAttribute(sample_mlp_kernel,
                         cudaFuncAttributeMaxDynamicSharedMemorySize, smem_bytes);
    sample_mlp_kernel<<<(B_ * T_) / NPTS, 256, smem_bytes>>>(coords, W1, b1, W2, b2, out);
}

// round 2
// speedup vs baseline: 1.9089x; 1.9089x over previous
#include <cuda_runtime.h>
#include <cuda_bf16.h>
#include <math.h>
#include <stdint.h>

#define B_   4
#define C_   256
#define D_   128
#define HW_  16384
#define W_   128
#define T_   16384
#define NPTS 128
#define MAX_DELTA 0.0009765625f   // 0.5/512

// 16 MB scratch: projected feature map in bf16, channel-last: vm[b][pix][d]
__device__ __nv_bfloat16 g_vm[(size_t)B_ * HW_ * D_];

// ---------------------------------------------------------------------------
// mma helpers
// ---------------------------------------------------------------------------
__device__ __forceinline__ uint32_t s2u(const void* p) {
    return (uint32_t)__cvta_generic_to_shared(p);
}
__device__ __forceinline__ void ldm_x4(uint32_t r[4], uint32_t addr) {
    asm volatile("ldmatrix.sync.aligned.m8n8.x4.shared.b16 {%0,%1,%2,%3}, [%4];\n"
        : "=r"(r[0]), "=r"(r[1]), "=r"(r[2]), "=r"(r[3]) : "r"(addr));
}
__device__ __forceinline__ void ldm_x4t(uint32_t r[4], uint32_t addr) {
    asm volatile("ldmatrix.sync.aligned.m8n8.x4.trans.shared.b16 {%0,%1,%2,%3}, [%4];\n"
        : "=r"(r[0]), "=r"(r[1]), "=r"(r[2]), "=r"(r[3]) : "r"(addr));
}
__device__ __forceinline__ void mma_bf16(float c[4], const uint32_t a[4], const uint32_t b[2]) {
    asm volatile("mma.sync.aligned.m16n8k16.row.col.f32.bf16.bf16.f32 "
        "{%0,%1,%2,%3}, {%4,%5,%6,%7}, {%8,%9}, {%0,%1,%2,%3};\n"
        : "+f"(c[0]), "+f"(c[1]), "+f"(c[2]), "+f"(c[3])
        : "r"(a[0]), "r"(a[1]), "r"(a[2]), "r"(a[3]), "r"(b[0]), "r"(b[1]));
}

// smem layout constants for proj
#define ASTR 136                       // AsT row stride (m dim), bf16 elems
#define BSTR 264                       // Bs row stride (k dim), bf16 elems
#define BS_ELEMS  (128 * BSTR)         // 33792
#define AST_ELEMS (32 * ASTR)          // 4352
#define PROJ_SMEM ((BS_ELEMS + 2 * AST_ELEMS) * 2)   // 84992 bytes

// ---------------------------------------------------------------------------
// Kernel 1: projection GEMM  vm[b, m, d] = sum_c fmap[b, c, m] * Wp[d, c]
// bf16 tensor cores. Block: 128 pixels x 128 d, K-chunks of 32 (double-buffered).
// 8 warps as 4(m) x 2(n); warp tile 32x64; mma m16n8k16.
// Whole Wp resident in smem as bf16 [n][k].
// ---------------------------------------------------------------------------
__global__ __launch_bounds__(256) void proj_kernel(const float* __restrict__ fmap,
                                                   const float* __restrict__ Wp)
{
    extern __shared__ __align__(16) __nv_bfloat16 sm[];
    __nv_bfloat16* Bs  = sm;               // [128 n][BSTR k]
    __nv_bfloat16* AsT = sm + BS_ELEMS;    // [2 buf][32 k][ASTR m]

    const int b      = blockIdx.y;
    const int m_base = blockIdx.x * 128;
    const int tid    = threadIdx.x;
    const int lane   = tid & 31, warp = tid >> 5;

    // Load all of Wp (128 x 256 fp32) -> bf16 Bs[n][k]
    for (int i = tid; i < 128 * 256 / 4; i += 256) {
        int idx = i * 4;
        int n = idx >> 8, k = idx & 255;
        float4 v = *(const float4*)&Wp[n * C_ + k];
        __nv_bfloat162* dst = (__nv_bfloat162*)&Bs[n * BSTR + k];
        dst[0] = __floats2bfloat162_rn(v.x, v.y);
        dst[1] = __floats2bfloat162_rn(v.z, v.w);
    }

    // fmap staging: thread (lk = tid>>3) owns one k-row, (l8 = tid&7) its m-slot
    const int lk = tid >> 3;
    const int l8 = tid & 7;
    const float* fbase = fmap + (size_t)b * C_ * HW_ + m_base;

    float4 st[4];
#pragma unroll
    for (int j = 0; j < 4; j++)
        st[j] = *(const float4*)&fbase[(size_t)lk * HW_ + (l8 + 8 * j) * 4];
    {
        __nv_bfloat16* A0 = AsT;
#pragma unroll
        for (int j = 0; j < 4; j++) {
            int m = (l8 + 8 * j) * 4;
            __nv_bfloat162* d2 = (__nv_bfloat162*)&A0[lk * ASTR + m];
            d2[0] = __floats2bfloat162_rn(st[j].x, st[j].y);
            d2[1] = __floats2bfloat162_rn(st[j].z, st[j].w);
        }
    }
    __syncthreads();

    const int wm = (warp & 3) * 32;
    const int wn = (warp >> 2) * 64;

    float acc[2][8][4];
#pragma unroll
    for (int mt = 0; mt < 2; mt++)
#pragma unroll
        for (int nt = 0; nt < 8; nt++)
#pragma unroll
            for (int q = 0; q < 4; q++) acc[mt][nt][q] = 0.f;

    const uint32_t bbase = s2u(Bs);

    for (int kc = 0; kc < 8; kc++) {
        if (kc < 7) {
#pragma unroll
            for (int j = 0; j < 4; j++)
                st[j] = *(const float4*)&fbase[(size_t)((kc + 1) * 32 + lk) * HW_ + (l8 + 8 * j) * 4];
        }
        const uint32_t abase = s2u(AsT + (kc & 1) * AST_ELEMS);

#pragma unroll
        for (int ks = 0; ks < 2; ks++) {
            uint32_t af[2][4];
#pragma unroll
            for (int mt = 0; mt < 2; mt++) {
                int row = ks * 16 + (lane & 7) + ((lane >> 4) << 3);
                int col = wm + mt * 16 + ((lane >> 3) & 1) * 8;
                ldm_x4t(af[mt], abase + (row * ASTR + col) * 2);
            }
            uint32_t bf[8][2];
#pragma unroll
            for (int np = 0; np < 4; np++) {
                int n = wn + np * 16 + (lane & 7) + ((lane >> 4) << 3);
                int k = kc * 32 + ks * 16 + ((lane >> 3) & 1) * 8;
                uint32_t r[4];
                ldm_x4(r, bbase + (n * BSTR + k) * 2);
                bf[2 * np][0]     = r[0];  bf[2 * np][1]     = r[1];
                bf[2 * np + 1][0] = r[2];  bf[2 * np + 1][1] = r[3];
            }
#pragma unroll
            for (int mt = 0; mt < 2; mt++)
#pragma unroll
                for (int nt = 0; nt < 8; nt++)
                    mma_bf16(acc[mt][nt], af[mt], bf[nt]);
        }

        if (kc < 7) {
            __nv_bfloat16* An = AsT + ((kc + 1) & 1) * AST_ELEMS;
#pragma unroll
            for (int j = 0; j < 4; j++) {
                int m = (l8 + 8 * j) * 4;
                __nv_bfloat162* d2 = (__nv_bfloat162*)&An[lk * ASTR + m];
                d2[0] = __floats2bfloat162_rn(st[j].x, st[j].y);
                d2[1] = __floats2bfloat162_rn(st[j].z, st[j].w);
            }
        }
        __syncthreads();
    }

    // epilogue: C frags -> bf16 g_vm[b][m][d]
    __nv_bfloat16* out = g_vm + ((size_t)b * HW_ + m_base) * D_;
#pragma unroll
    for (int mt = 0; mt < 2; mt++) {
#pragma unroll
        for (int nt = 0; nt < 8; nt++) {
            int r0 = wm + mt * 16 + (lane >> 2);
            int d0 = wn + nt * 8 + (lane & 3) * 2;
            *(__nv_bfloat162*)&out[(size_t)r0 * D_ + d0] =
                __floats2bfloat162_rn(acc[mt][nt][0], acc[mt][nt][1]);
            *(__nv_bfloat162*)&out[(size_t)(r0 + 8) * D_ + d0] =
                __floats2bfloat162_rn(acc[mt][nt][2], acc[mt][nt][3]);
        }
    }
}

// ---------------------------------------------------------------------------
// Kernel 2: fused 4x4 separable stencil sampling (bf16 vm) + 2-layer MLP.
// ---------------------------------------------------------------------------
__global__ __launch_bounds__(256) void sample_mlp_kernel(
    const float* __restrict__ coords, const float* __restrict__ W1,
    const float* __restrict__ b1,     const float* __restrict__ W2,
    const float* __restrict__ b2,     float* __restrict__ out)
{
    extern __shared__ float smem[];
    float* featS = smem;                       // 128*128 floats, [pt][ch]
    float* BsW   = smem + 128 * 128;           // 16*128 floats,  [k][j]
    float* red   = BsW  + 16 * 128;            // 16*258 floats

    const int tid  = threadIdx.x;
    const int lane = tid & 31, warp = tid >> 5;
    const int ptBase = blockIdx.x * NPTS;

    // ---------------- Phase 1: sampling (bf16 vm, lane owns 4 channels) ----
    const float inv9 = 1.f / 9.f;
    for (int pp = 0; pp < NPTS / 8; pp++) {
        int pt  = warp * (NPTS / 8) + pp;
        int gpt = ptBase + pt;
        int b   = gpt >> 14;

        float cx = coords[2 * gpt], cy = coords[2 * gpt + 1];
        float ix = cx * 127.f, iy = cy * 127.f;
        float xf = floorf(ix), yf = floorf(iy);
        int   x0 = (int)xf,    y0 = (int)yf;
        float fx = ix - xf,    fy = iy - yf;
        float Xw[4] = {1.f - fx, 1.f, 1.f, fx};
        float Yw[4] = {1.f - fy, 1.f, 1.f, fy};

        float4 acc = make_float4(0.f, 0.f, 0.f, 0.f);
        const uint2* vmb = ((const uint2*)g_vm) + (size_t)b * HW_ * 32 + lane;
#pragma unroll
        for (int j = 0; j < 4; j++) {
            int py = y0 - 1 + j;
            if ((unsigned)py > 127u) continue;
#pragma unroll
            for (int i = 0; i < 4; i++) {
                int px = x0 - 1 + i;
                if ((unsigned)px > 127u) continue;
                float w = Yw[j] * Xw[i];
                uint2 v = vmb[(size_t)(py * W_ + px) * 32];
                float2 f01 = __bfloat1622float2(*(const __nv_bfloat162*)&v.x);
                float2 f23 = __bfloat1622float2(*(const __nv_bfloat162*)&v.y);
                acc.x = fmaf(w, f01.x, acc.x);
                acc.y = fmaf(w, f01.y, acc.y);
                acc.z = fmaf(w, f23.x, acc.z);
                acc.w = fmaf(w, f23.y, acc.w);
            }
        }
        acc.x *= inv9; acc.y *= inv9; acc.z *= inv9; acc.w *= inv9;
        ((float4*)(featS + pt * 128))[lane] = acc;
    }
    __syncthreads();

    // ---------------- Phase 2: MLP GEMM (fp32 SIMT) ----------------
    const int td = tid & 15, tm = tid >> 4;
    const int m0 = tm * 8,   j0 = td * 8;

    float acc[8][8];
#pragma unroll
    for (int i = 0; i < 8; i++)
#pragma unroll
        for (int j = 0; j < 8; j++) acc[i][j] = 0.f;

    for (int k0 = 0; k0 < 128; k0 += 16) {
#pragma unroll
        for (int i = 0; i < 8; i++) {
            int k = tid & 15;
            int j = i * 16 + (tid >> 4);
            BsW[k * 128 + j] = W1[j * 128 + k0 + k];
        }
        __syncthreads();
#pragma unroll
        for (int kk = 0; kk < 16; kk++) {
            float a[8];
#pragma unroll
            for (int i = 0; i < 8; i++) a[i] = featS[(m0 + i) * 128 + k0 + kk];
            float4 c0 = *(const float4*)&BsW[kk * 128 + j0];
            float4 c1 = *(const float4*)&BsW[kk * 128 + j0 + 4];
            float bb[8] = {c0.x, c0.y, c0.z, c0.w, c1.x, c1.y, c1.z, c1.w};
#pragma unroll
            for (int i = 0; i < 8; i++)
#pragma unroll
                for (int j = 0; j < 8; j++)
                    acc[i][j] = fmaf(a[i], bb[j], acc[i][j]);
        }
        __syncthreads();
    }

    // epilogue: h = relu(acc + b1); partial (W2 @ h) per thread -> smem reduce
    float b1v[8], w20[8], w21[8];
#pragma unroll
    for (int i = 0; i < 8; i++) {
        b1v[i] = b1[j0 + i];
        w20[i] = W2[j0 + i];
        w21[i] = W2[128 + j0 + i];
    }
#pragma unroll
    for (int mi = 0; mi < 8; mi++) {
        float s0 = 0.f, s1 = 0.f;
#pragma unroll
        for (int ji = 0; ji < 8; ji++) {
            float h = acc[mi][ji] + b1v[ji];
            h = fmaxf(h, 0.f);
            s0 = fmaf(w20[ji], h, s0);
            s1 = fmaf(w21[ji], h, s1);
        }
        red[td * 258 + (m0 + mi) * 2 + 0] = s0;
        red[td * 258 + (m0 + mi) * 2 + 1] = s1;
    }
    __syncthreads();

    {
        int pt = tid >> 1, c = tid & 1;
        float s = b2[c];
#pragma unroll
        for (int g = 0; g < 16; g++) s += red[g * 258 + pt * 2 + c];
        float v = tanhf(s) * MAX_DELTA;
        int gi = (ptBase + pt) * 2 + c;
        out[gi] = coords[gi] + v;
    }
}

// ---------------------------------------------------------------------------
extern "C" void kernel_launch(void* const* d_in, const int* in_sizes, int n_in,
                              void* d_out, int out_size)
{
    (void)in_sizes; (void)n_in; (void)out_size;
    const float* fmap   = (const float*)d_in[0];
    const float* coords = (const float*)d_in[1];
    const float* Wp     = (const float*)d_in[2];
    const float* W1     = (const float*)d_in[3];
    const float* b1     = (const float*)d_in[4];
    const float* W2     = (const float*)d_in[5];
    const float* b2     = (const float*)d_in[6];
    float* out = (float*)d_out;

    cudaFuncSetAttribute(proj_kernel,
                         cudaFuncAttributeMaxDynamicSharedMemorySize, PROJ_SMEM);
    proj_kernel<<<dim3(HW_ / 128, B_), 256, PROJ_SMEM>>>(fmap, Wp);

    const int smem_bytes = (128 * 128 + 16 * 128 + 16 * 258) * 4;  // 90240 B
    cudaFuncSetAttribute(sample_mlp_kernel,
                         cudaFuncAttributeMaxDynamicSharedMemorySize, smem_bytes);
    sample_mlp_kernel<<<(B_ * T_) / NPTS, 256, smem_bytes>>>(coords, W1, b1, W2, b2, out);
}

// round 3
// speedup vs baseline: 3.7800x; 1.9802x over previous
#include <cuda_runtime.h>
#include <cuda_bf16.h>
#include <math.h>
#include <stdint.h>

#define B_   4
#define C_   256
#define D_   128
#define HW_  16384
#define W_   128
#define T_   16384
#define NPTS 128
#define MAX_DELTA 0.0009765625f   // 0.5/512

// 16 MB scratch: projected feature map in bf16, channel-last: vm[b][pix][d]
__device__ __nv_bfloat16 g_vm[(size_t)B_ * HW_ * D_];

// ---------------------------------------------------------------------------
// mma helpers
// ---------------------------------------------------------------------------
__device__ __forceinline__ uint32_t s2u(const void* p) {
    return (uint32_t)__cvta_generic_to_shared(p);
}
__device__ __forceinline__ void ldm_x4(uint32_t r[4], uint32_t addr) {
    asm volatile("ldmatrix.sync.aligned.m8n8.x4.shared.b16 {%0,%1,%2,%3}, [%4];\n"
        : "=r"(r[0]), "=r"(r[1]), "=r"(r[2]), "=r"(r[3]) : "r"(addr));
}
__device__ __forceinline__ void ldm_x4t(uint32_t r[4], uint32_t addr) {
    asm volatile("ldmatrix.sync.aligned.m8n8.x4.trans.shared.b16 {%0,%1,%2,%3}, [%4];\n"
        : "=r"(r[0]), "=r"(r[1]), "=r"(r[2]), "=r"(r[3]) : "r"(addr));
}
__device__ __forceinline__ void mma_bf16(float c[4], const uint32_t a[4], const uint32_t b[2]) {
    asm volatile("mma.sync.aligned.m16n8k16.row.col.f32.bf16.bf16.f32 "
        "{%0,%1,%2,%3}, {%4,%5,%6,%7}, {%8,%9}, {%0,%1,%2,%3};\n"
        : "+f"(c[0]), "+f"(c[1]), "+f"(c[2]), "+f"(c[3])
        : "r"(a[0]), "r"(a[1]), "r"(a[2]), "r"(a[3]), "r"(b[0]), "r"(b[1]));
}

// smem layout constants for proj
#define ASTR 136                       // AsT row stride (m dim), bf16 elems
#define BSTR 264                       // Bs row stride (k dim), bf16 elems
#define BS_ELEMS  (128 * BSTR)         // 33792
#define AST_ELEMS (32 * ASTR)          // 4352
#define PROJ_SMEM ((BS_ELEMS + 2 * AST_ELEMS) * 2)   // 84992 bytes

// ---------------------------------------------------------------------------
// Kernel 1: projection GEMM  vm[b, m, d] = sum_c fmap[b, c, m] * Wp[d, c]
// (unchanged from R2: near HBM-read floor)
// ---------------------------------------------------------------------------
__global__ __launch_bounds__(256) void proj_kernel(const float* __restrict__ fmap,
                                                   const float* __restrict__ Wp)
{
    extern __shared__ __align__(16) __nv_bfloat16 sm[];
    __nv_bfloat16* Bs  = sm;               // [128 n][BSTR k]
    __nv_bfloat16* AsT = sm + BS_ELEMS;    // [2 buf][32 k][ASTR m]

    const int b      = blockIdx.y;
    const int m_base = blockIdx.x * 128;
    const int tid    = threadIdx.x;
    const int lane   = tid & 31, warp = tid >> 5;

    for (int i = tid; i < 128 * 256 / 4; i += 256) {
        int idx = i * 4;
        int n = idx >> 8, k = idx & 255;
        float4 v = *(const float4*)&Wp[n * C_ + k];
        __nv_bfloat162* dst = (__nv_bfloat162*)&Bs[n * BSTR + k];
        dst[0] = __floats2bfloat162_rn(v.x, v.y);
        dst[1] = __floats2bfloat162_rn(v.z, v.w);
    }

    const int lk = tid >> 3;
    const int l8 = tid & 7;
    const float* fbase = fmap + (size_t)b * C_ * HW_ + m_base;

    float4 st[4];
#pragma unroll
    for (int j = 0; j < 4; j++)
        st[j] = *(const float4*)&fbase[(size_t)lk * HW_ + (l8 + 8 * j) * 4];
    {
        __nv_bfloat16* A0 = AsT;
#pragma unroll
        for (int j = 0; j < 4; j++) {
            int m = (l8 + 8 * j) * 4;
            __nv_bfloat162* d2 = (__nv_bfloat162*)&A0[lk * ASTR + m];
            d2[0] = __floats2bfloat162_rn(st[j].x, st[j].y);
            d2[1] = __floats2bfloat162_rn(st[j].z, st[j].w);
        }
    }
    __syncthreads();

    const int wm = (warp & 3) * 32;
    const int wn = (warp >> 2) * 64;

    float acc[2][8][4];
#pragma unroll
    for (int mt = 0; mt < 2; mt++)
#pragma unroll
        for (int nt = 0; nt < 8; nt++)
#pragma unroll
            for (int q = 0; q < 4; q++) acc[mt][nt][q] = 0.f;

    const uint32_t bbase = s2u(Bs);

    for (int kc = 0; kc < 8; kc++) {
        if (kc < 7) {
#pragma unroll
            for (int j = 0; j < 4; j++)
                st[j] = *(const float4*)&fbase[(size_t)((kc + 1) * 32 + lk) * HW_ + (l8 + 8 * j) * 4];
        }
        const uint32_t abase = s2u(AsT + (kc & 1) * AST_ELEMS);

#pragma unroll
        for (int ks = 0; ks < 2; ks++) {
            uint32_t af[2][4];
#pragma unroll
            for (int mt = 0; mt < 2; mt++) {
                int row = ks * 16 + (lane & 7) + ((lane >> 4) << 3);
                int col = wm + mt * 16 + ((lane >> 3) & 1) * 8;
                ldm_x4t(af[mt], abase + (row * ASTR + col) * 2);
            }
            uint32_t bf[8][2];
#pragma unroll
            for (int np = 0; np < 4; np++) {
                int n = wn + np * 16 + (lane & 7) + ((lane >> 4) << 3);
                int k = kc * 32 + ks * 16 + ((lane >> 3) & 1) * 8;
                uint32_t r[4];
                ldm_x4(r, bbase + (n * BSTR + k) * 2);
                bf[2 * np][0]     = r[0];  bf[2 * np][1]     = r[1];
                bf[2 * np + 1][0] = r[2];  bf[2 * np + 1][1] = r[3];
            }
#pragma unroll
            for (int mt = 0; mt < 2; mt++)
#pragma unroll
                for (int nt = 0; nt < 8; nt++)
                    mma_bf16(acc[mt][nt], af[mt], bf[nt]);
        }

        if (kc < 7) {
            __nv_bfloat16* An = AsT + ((kc + 1) & 1) * AST_ELEMS;
#pragma unroll
            for (int j = 0; j < 4; j++) {
                int m = (l8 + 8 * j) * 4;
                __nv_bfloat162* d2 = (__nv_bfloat162*)&An[lk * ASTR + m];
                d2[0] = __floats2bfloat162_rn(st[j].x, st[j].y);
                d2[1] = __floats2bfloat162_rn(st[j].z, st[j].w);
            }
        }
        __syncthreads();
    }

    __nv_bfloat16* out = g_vm + ((size_t)b * HW_ + m_base) * D_;
#pragma unroll
    for (int mt = 0; mt < 2; mt++) {
#pragma unroll
        for (int nt = 0; nt < 8; nt++) {
            int r0 = wm + mt * 16 + (lane >> 2);
            int d0 = wn + nt * 8 + (lane & 3) * 2;
            *(__nv_bfloat162*)&out[(size_t)r0 * D_ + d0] =
                __floats2bfloat162_rn(acc[mt][nt][0], acc[mt][nt][1]);
            *(__nv_bfloat162*)&out[(size_t)(r0 + 8) * D_ + d0] =
                __floats2bfloat162_rn(acc[mt][nt][2], acc[mt][nt][3]);
        }
    }
}

// ---------------------------------------------------------------------------
// Kernel 2: fused branch-free 4x4 stencil sampling + bf16 mma MLP + tanh.
// smem: featS bf16 [128 pt][FSTR], W1s bf16 [128 j][FSTR]; red aliases featS.
// ---------------------------------------------------------------------------
#define FSTR 136
#define FEAT_ELEMS (128 * FSTR)
#define SAMP_SMEM  (2 * FEAT_ELEMS * 2)    // 69632 bytes

__global__ __launch_bounds__(256) void sample_mlp_kernel(
    const float* __restrict__ coords, const float* __restrict__ W1,
    const float* __restrict__ b1,     const float* __restrict__ W2,
    const float* __restrict__ b2,     float* __restrict__ out)
{
    extern __shared__ __align__(16) __nv_bfloat16 smb[];
    __nv_bfloat16* featS = smb;                 // [128][FSTR]
    __nv_bfloat16* W1s   = smb + FEAT_ELEMS;    // [128][FSTR]
    float*         red   = (float*)smb;         // aliases featS after GEMM

    const int tid  = threadIdx.x;
    const int lane = tid & 31, warp = tid >> 5;
    const int ptBase = blockIdx.x * NPTS;

    // ---- Load W1 (fp32 -> bf16 smem), independent of sampling ----
    for (int i = tid; i < 128 * 128 / 4; i += 256) {
        int idx = i * 4;
        int j = idx >> 7, k = idx & 127;
        float4 v = *(const float4*)&W1[j * 128 + k];
        __nv_bfloat162* dst = (__nv_bfloat162*)&W1s[j * FSTR + k];
        dst[0] = __floats2bfloat162_rn(v.x, v.y);
        dst[1] = __floats2bfloat162_rn(v.z, v.w);
    }

    // ---------------- Phase 1: branch-free sampling ----------------
    const float inv9 = 1.f / 9.f;
    for (int pp = 0; pp < NPTS / 8; pp++) {
        int pt  = warp * (NPTS / 8) + pp;
        int gpt = ptBase + pt;
        int b   = gpt >> 14;

        float cx = coords[2 * gpt], cy = coords[2 * gpt + 1];
        float ix = cx * 127.f, iy = cy * 127.f;
        float xf = floorf(ix), yf = floorf(iy);
        int   x0 = (int)xf,    y0 = (int)yf;
        float fx = ix - xf,    fy = iy - yf;
        float Xw[4] = {1.f - fx, 1.f, 1.f, fx};
        float Yw[4] = {1.f - fy, 1.f, 1.f, fy};

        // clamped indices + zeroed OOB weights (no branches)
        float wx[4], wy[4];
        int   px[4], py[4];
#pragma unroll
        for (int i = 0; i < 4; i++) {
            int x = x0 - 1 + i;
            bool vx = ((unsigned)x < 128u);
            wx[i] = vx ? Xw[i] : 0.f;
            px[i] = vx ? x : 0;
            int y = y0 - 1 + i;
            bool vy = ((unsigned)y < 128u);
            wy[i] = vy ? Yw[i] : 0.f;
            py[i] = vy ? y : 0;
        }

        const uint2* vmb = ((const uint2*)g_vm) + (size_t)b * HW_ * 32 + lane;
        uint32_t off[16];
        float    wv[16];
#pragma unroll
        for (int j = 0; j < 4; j++)
#pragma unroll
            for (int i = 0; i < 4; i++) {
                off[j * 4 + i] = (uint32_t)(py[j] * W_ + px[i]) * 32u;
                wv[j * 4 + i]  = wy[j] * wx[i];
            }

        uint2 v[16];
#pragma unroll
        for (int t = 0; t < 16; t++) v[t] = vmb[off[t]];

        float4 acc = make_float4(0.f, 0.f, 0.f, 0.f);
#pragma unroll
        for (int t = 0; t < 16; t++) {
            float2 f01 = __bfloat1622float2(*(const __nv_bfloat162*)&v[t].x);
            float2 f23 = __bfloat1622float2(*(const __nv_bfloat162*)&v[t].y);
            float w = wv[t];
            acc.x = fmaf(w, f01.x, acc.x);
            acc.y = fmaf(w, f01.y, acc.y);
            acc.z = fmaf(w, f23.x, acc.z);
            acc.w = fmaf(w, f23.y, acc.w);
        }
        __nv_bfloat162 p01 = __floats2bfloat162_rn(acc.x * inv9, acc.y * inv9);
        __nv_bfloat162 p23 = __floats2bfloat162_rn(acc.z * inv9, acc.w * inv9);
        uint2 pk;
        pk.x = *(uint32_t*)&p01; pk.y = *(uint32_t*)&p23;
        *(uint2*)&featS[pt * FSTR + lane * 4] = pk;
    }
    __syncthreads();

    // ---------------- Phase 2: bf16 mma GEMM, zero barriers ----------------
    const int wm = (warp & 3) * 32;
    const int wn = (warp >> 2) * 64;

    float acc[2][8][4];
#pragma unroll
    for (int mt = 0; mt < 2; mt++)
#pragma unroll
        for (int nt = 0; nt < 8; nt++)
#pragma unroll
            for (int q = 0; q < 4; q++) acc[mt][nt][q] = 0.f;

    const uint32_t abase = s2u(featS);
    const uint32_t bbase = s2u(W1s);

#pragma unroll
    for (int kc = 0; kc < 8; kc++) {
        int k0 = kc * 16;
        uint32_t af[2][4];
#pragma unroll
        for (int mt = 0; mt < 2; mt++) {
            int row = wm + mt * 16 + (lane & 15);
            int col = k0 + ((lane >> 4) << 3);
            ldm_x4(af[mt], abase + (row * FSTR + col) * 2);
        }
        uint32_t bf[8][2];
#pragma unroll
        for (int np = 0; np < 4; np++) {
            int n = wn + np * 16 + (lane & 7) + ((lane >> 4) << 3);
            int k = k0 + ((lane >> 3) & 1) * 8;
            uint32_t r[4];
            ldm_x4(r, bbase + (n * FSTR + k) * 2);
            bf[2 * np][0]     = r[0];  bf[2 * np][1]     = r[1];
            bf[2 * np + 1][0] = r[2];  bf[2 * np + 1][1] = r[3];
        }
#pragma unroll
        for (int mt = 0; mt < 2; mt++)
#pragma unroll
            for (int nt = 0; nt < 8; nt++)
                mma_bf16(acc[mt][nt], af[mt], bf[nt]);
    }

    // ---- Epilogue: h = relu(acc + b1), partial W2 @ h ----
    float2 b1v[8], w20v[8], w21v[8];
#pragma unroll
    for (int nt = 0; nt < 8; nt++) {
        int j = wn + nt * 8 + (lane & 3) * 2;
        b1v[nt]  = *(const float2*)&b1[j];
        w20v[nt] = *(const float2*)&W2[j];
        w21v[nt] = *(const float2*)&W2[128 + j];
    }
    // partials per (mt, half): 4 rows per thread
    float s0[2][2], s1[2][2];
#pragma unroll
    for (int mt = 0; mt < 2; mt++)
#pragma unroll
        for (int hh = 0; hh < 2; hh++) { s0[mt][hh] = 0.f; s1[mt][hh] = 0.f; }
#pragma unroll
    for (int mt = 0; mt < 2; mt++)
#pragma unroll
        for (int nt = 0; nt < 8; nt++) {
            float h00 = fmaxf(acc[mt][nt][0] + b1v[nt].x, 0.f);
            float h01 = fmaxf(acc[mt][nt][1] + b1v[nt].y, 0.f);
            float h10 = fmaxf(acc[mt][nt][2] + b1v[nt].x, 0.f);
            float h11 = fmaxf(acc[mt][nt][3] + b1v[nt].y, 0.f);
            s0[mt][0] = fmaf(w20v[nt].x, h00, s0[mt][0]);
            s0[mt][0] = fmaf(w20v[nt].y, h01, s0[mt][0]);
            s1[mt][0] = fmaf(w21v[nt].x, h00, s1[mt][0]);
            s1[mt][0] = fmaf(w21v[nt].y, h01, s1[mt][0]);
            s0[mt][1] = fmaf(w20v[nt].x, h10, s0[mt][1]);
            s0[mt][1] = fmaf(w20v[nt].y, h11, s0[mt][1]);
            s1[mt][1] = fmaf(w21v[nt].x, h10, s1[mt][1]);
            s1[mt][1] = fmaf(w21v[nt].y, h11, s1[mt][1]);
        }

    __syncthreads();   // all featS reads done; safe to alias red

    // red[p][row][c], p = (warp_n * 4 + (lane & 3)) in 0..7
    int p = (warp >> 2) * 4 + (lane & 3);
#pragma unroll
    for (int mt = 0; mt < 2; mt++)
#pragma unroll
        for (int hh = 0; hh < 2; hh++) {
            int row = wm + mt * 16 + (lane >> 2) + 8 * hh;
            red[(p * 128 + row) * 2 + 0] = s0[mt][hh];
            red[(p * 128 + row) * 2 + 1] = s1[mt][hh];
        }
    __syncthreads();

    {
        int pt = tid >> 1, c = tid & 1;
        float s = b2[c];
#pragma unroll
        for (int g = 0; g < 8; g++) s += red[(g * 128 + pt) * 2 + c];
        float v = tanhf(s) * MAX_DELTA;
        int gi = (ptBase + pt) * 2 + c;
        out[gi] = coords[gi] + v;
    }
}

// ---------------------------------------------------------------------------
extern "C" void kernel_launch(void* const* d_in, const int* in_sizes, int n_in,
                              void* d_out, int out_size)
{
    (void)in_sizes; (void)n_in; (void)out_size;
    const float* fmap   = (const float*)d_in[0];
    const float* coords = (const float*)d_in[1];
    const float* Wp     = (const float*)d_in[2];
    const float* W1     = (const float*)d_in[3];
    const float* b1     = (const float*)d_in[4];
    const float* W2     = (const float*)d_in[5];
    const float* b2     = (const float*)d_in[6];
    float* out = (float*)d_out;

    cudaFuncSetAttribute(proj_kernel,
                         cudaFuncAttributeMaxDynamicSharedMemorySize, PROJ_SMEM);
    proj_kernel<<<dim3(HW_ / 128, B_), 256, PROJ_SMEM>>>(fmap, Wp);

    cudaFuncSetAttribute(sample_mlp_kernel,
                         cudaFuncAttributeMaxDynamicSharedMemorySize, SAMP_SMEM);
    sample_mlp_kernel<<<(B_ * T_) / NPTS, 256, SAMP_SMEM>>>(coords, W1, b1, W2, b2, out);
}

// round 4
// speedup vs baseline: 4.1070x; 1.0865x over previous
#include <cuda_runtime.h>
#include <cuda_bf16.h>
#include <cuda_fp16.h>
#include <math.h>
#include <stdint.h>

#define B_   4
#define C_   256
#define D_   128
#define HW_  16384
#define W_   128
#define T_   16384
#define MAX_DELTA 0.0009765625f   // 0.5/512

// 8 MB scratch: projected feature map in fp8 e4m3, channel-last: vm[b][pix][d]
__device__ uint8_t g_vm8[(size_t)B_ * HW_ * D_];
// 16 MB scratch: sampled features fp16 [pt][d]
__device__ __half g_feat[(size_t)B_ * T_ * D_];

// ---------------------------------------------------------------------------
// helpers
// ---------------------------------------------------------------------------
__device__ __forceinline__ uint32_t s2u(const void* p) {
    return (uint32_t)__cvta_generic_to_shared(p);
}
__device__ __forceinline__ void ldm_x4(uint32_t r[4], uint32_t addr) {
    asm volatile("ldmatrix.sync.aligned.m8n8.x4.shared.b16 {%0,%1,%2,%3}, [%4];\n"
        : "=r"(r[0]), "=r"(r[1]), "=r"(r[2]), "=r"(r[3]) : "r"(addr));
}
__device__ __forceinline__ void ldm_x4t(uint32_t r[4], uint32_t addr) {
    asm volatile("ldmatrix.sync.aligned.m8n8.x4.trans.shared.b16 {%0,%1,%2,%3}, [%4];\n"
        : "=r"(r[0]), "=r"(r[1]), "=r"(r[2]), "=r"(r[3]) : "r"(addr));
}
__device__ __forceinline__ void mma_bf16(float c[4], const uint32_t a[4], const uint32_t b[2]) {
    asm volatile("mma.sync.aligned.m16n8k16.row.col.f32.bf16.bf16.f32 "
        "{%0,%1,%2,%3}, {%4,%5,%6,%7}, {%8,%9}, {%0,%1,%2,%3};\n"
        : "+f"(c[0]), "+f"(c[1]), "+f"(c[2]), "+f"(c[3])
        : "r"(a[0]), "r"(a[1]), "r"(a[2]), "r"(a[3]), "r"(b[0]), "r"(b[1]));
}
__device__ __forceinline__ void mma_f16(float c[4], const uint32_t a[4], const uint32_t b[2]) {
    asm volatile("mma.sync.aligned.m16n8k16.row.col.f32.f16.f16.f32 "
        "{%0,%1,%2,%3}, {%4,%5,%6,%7}, {%8,%9}, {%0,%1,%2,%3};\n"
        : "+f"(c[0]), "+f"(c[1]), "+f"(c[2]), "+f"(c[3])
        : "r"(a[0]), "r"(a[1]), "r"(a[2]), "r"(a[3]), "r"(b[0]), "r"(b[1]));
}
// pack two fp32 -> e4m3x2 (lo at low byte)
__device__ __forceinline__ uint16_t pack_e4m3x2(float lo, float hi) {
    uint16_t r;
    asm("cvt.rn.satfinite.e4m3x2.f32 %0, %1, %2;" : "=h"(r) : "f"(hi), "f"(lo));
    return r;
}
// unpack e4m3x2 -> half2 (byte0 -> .x)
__device__ __forceinline__ __half2 e4m3x2_to_h2(uint32_t u) {
    uint32_t r;
    asm("cvt.rn.f16x2.e4m3x2 %0, %1;" : "=r"(r) : "h"((uint16_t)u));
    return *(__half2*)&r;
}

// smem layout constants for proj
#define ASTR 136
#define BSTR 264
#define BS_ELEMS  (128 * BSTR)
#define AST_ELEMS (32 * ASTR)
#define PROJ_SMEM ((BS_ELEMS + 2 * AST_ELEMS) * 2)   // 84992 bytes

// ---------------------------------------------------------------------------
// Kernel 1: projection GEMM -> fp8 vm
// ---------------------------------------------------------------------------
__global__ __launch_bounds__(256) void proj_kernel(const float* __restrict__ fmap,
                                                   const float* __restrict__ Wp)
{
    extern __shared__ __align__(16) __nv_bfloat16 sm[];
    __nv_bfloat16* Bs  = sm;               // [128 n][BSTR k]
    __nv_bfloat16* AsT = sm + BS_ELEMS;    // [2 buf][32 k][ASTR m]

    const int b      = blockIdx.y;
    const int m_base = blockIdx.x * 128;
    const int tid    = threadIdx.x;
    const int lane   = tid & 31, warp = tid >> 5;

    for (int i = tid; i < 128 * 256 / 4; i += 256) {
        int idx = i * 4;
        int n = idx >> 8, k = idx & 255;
        float4 v = *(const float4*)&Wp[n * C_ + k];
        __nv_bfloat162* dst = (__nv_bfloat162*)&Bs[n * BSTR + k];
        dst[0] = __floats2bfloat162_rn(v.x, v.y);
        dst[1] = __floats2bfloat162_rn(v.z, v.w);
    }

    const int lk = tid >> 3;
    const int l8 = tid & 7;
    const float* fbase = fmap + (size_t)b * C_ * HW_ + m_base;

    float4 st[4];
#pragma unroll
    for (int j = 0; j < 4; j++)
        st[j] = *(const float4*)&fbase[(size_t)lk * HW_ + (l8 + 8 * j) * 4];
    {
        __nv_bfloat16* A0 = AsT;
#pragma unroll
        for (int j = 0; j < 4; j++) {
            int m = (l8 + 8 * j) * 4;
            __nv_bfloat162* d2 = (__nv_bfloat162*)&A0[lk * ASTR + m];
            d2[0] = __floats2bfloat162_rn(st[j].x, st[j].y);
            d2[1] = __floats2bfloat162_rn(st[j].z, st[j].w);
        }
    }
    __syncthreads();

    const int wm = (warp & 3) * 32;
    const int wn = (warp >> 2) * 64;

    float acc[2][8][4];
#pragma unroll
    for (int mt = 0; mt < 2; mt++)
#pragma unroll
        for (int nt = 0; nt < 8; nt++)
#pragma unroll
            for (int q = 0; q < 4; q++) acc[mt][nt][q] = 0.f;

    const uint32_t bbase = s2u(Bs);

    for (int kc = 0; kc < 8; kc++) {
        if (kc < 7) {
#pragma unroll
            for (int j = 0; j < 4; j++)
                st[j] = *(const float4*)&fbase[(size_t)((kc + 1) * 32 + lk) * HW_ + (l8 + 8 * j) * 4];
        }
        const uint32_t abase = s2u(AsT + (kc & 1) * AST_ELEMS);

#pragma unroll
        for (int ks = 0; ks < 2; ks++) {
            uint32_t af[2][4];
#pragma unroll
            for (int mt = 0; mt < 2; mt++) {
                int row = ks * 16 + (lane & 7) + ((lane >> 4) << 3);
                int col = wm + mt * 16 + ((lane >> 3) & 1) * 8;
                ldm_x4t(af[mt], abase + (row * ASTR + col) * 2);
            }
            uint32_t bf[8][2];
#pragma unroll
            for (int np = 0; np < 4; np++) {
                int n = wn + np * 16 + (lane & 7) + ((lane >> 4) << 3);
                int k = kc * 32 + ks * 16 + ((lane >> 3) & 1) * 8;
                uint32_t r[4];
                ldm_x4(r, bbase + (n * BSTR + k) * 2);
                bf[2 * np][0]     = r[0];  bf[2 * np][1]     = r[1];
                bf[2 * np + 1][0] = r[2];  bf[2 * np + 1][1] = r[3];
            }
#pragma unroll
            for (int mt = 0; mt < 2; mt++)
#pragma unroll
                for (int nt = 0; nt < 8; nt++)
                    mma_bf16(acc[mt][nt], af[mt], bf[nt]);
        }

        if (kc < 7) {
            __nv_bfloat16* An = AsT + ((kc + 1) & 1) * AST_ELEMS;
#pragma unroll
            for (int j = 0; j < 4; j++) {
                int m = (l8 + 8 * j) * 4;
                __nv_bfloat162* d2 = (__nv_bfloat162*)&An[lk * ASTR + m];
                d2[0] = __floats2bfloat162_rn(st[j].x, st[j].y);
                d2[1] = __floats2bfloat162_rn(st[j].z, st[j].w);
            }
        }
        __syncthreads();
    }

    // epilogue: C frags -> fp8 g_vm8[b][m][d]
    uint8_t* out = g_vm8 + ((size_t)b * HW_ + m_base) * D_;
#pragma unroll
    for (int mt = 0; mt < 2; mt++) {
#pragma unroll
        for (int nt = 0; nt < 8; nt++) {
            int r0 = wm + mt * 16 + (lane >> 2);
            int d0 = wn + nt * 8 + (lane & 3) * 2;
            *(uint16_t*)&out[(size_t)r0 * D_ + d0] =
                pack_e4m3x2(acc[mt][nt][0], acc[mt][nt][1]);
            *(uint16_t*)&out[(size_t)(r0 + 8) * D_ + d0] =
                pack_e4m3x2(acc[mt][nt][2], acc[mt][nt][3]);
        }
    }
}

// ---------------------------------------------------------------------------
// Kernel 2: branch-free 4x4 stencil sampler. fp8 gathers, fp16 accumulation.
// Warp per point, lane owns 4 channels (LDG.32). No smem. High occupancy.
// ---------------------------------------------------------------------------
__global__ __launch_bounds__(256, 4) void sample_kernel(const float* __restrict__ coords)
{
    const int tid  = threadIdx.x;
    const int lane = tid & 31, warp = tid >> 5;
    const int ptBase = blockIdx.x * 64 + warp * 8;
    const float inv9 = 1.f / 9.f;

#pragma unroll 1
    for (int i = 0; i < 8; i++) {
        int gpt = ptBase + i;
        int b   = gpt >> 14;

        float cx = coords[2 * gpt], cy = coords[2 * gpt + 1];
        float ix = cx * 127.f, iy = cy * 127.f;
        float xf = floorf(ix), yf = floorf(iy);
        int   x0 = (int)xf,    y0 = (int)yf;
        float fx = ix - xf,    fy = iy - yf;
        float Xw[4] = {1.f - fx, 1.f, 1.f, fx};
        float Yw[4] = {1.f - fy, 1.f, 1.f, fy};

        float wx[4], wy[4];
        int   px[4], py[4];
#pragma unroll
        for (int q = 0; q < 4; q++) {
            int x = x0 - 1 + q;
            bool vx = ((unsigned)x < 128u);
            wx[q] = vx ? Xw[q] : 0.f;
            px[q] = vx ? x : 0;
            int y = y0 - 1 + q;
            bool vy = ((unsigned)y < 128u);
            wy[q] = vy ? (Yw[q] * inv9) : 0.f;   // fold 1/9 into y weights
            py[q] = vy ? y : 0;
        }

        const uint32_t* vmb = ((const uint32_t*)g_vm8) + (size_t)b * HW_ * 32 + lane;
        uint32_t off[16];
#pragma unroll
        for (int j = 0; j < 4; j++)
#pragma unroll
            for (int q = 0; q < 4; q++)
                off[j * 4 + q] = (uint32_t)(py[j] * W_ + px[q]) * 32u;

        uint32_t v[16];
#pragma unroll
        for (int t = 0; t < 16; t++) v[t] = vmb[off[t]];

        __half2 a01 = __half2(__float2half(0.f), __float2half(0.f));
        __half2 a23 = a01;
#pragma unroll
        for (int j = 0; j < 4; j++)
#pragma unroll
            for (int q = 0; q < 4; q++) {
                int t = j * 4 + q;
                __half2 w2 = __float2half2_rn(wy[j] * wx[q]);
                a01 = __hfma2(e4m3x2_to_h2(v[t] & 0xffffu), w2, a01);
                a23 = __hfma2(e4m3x2_to_h2(v[t] >> 16), w2, a23);
            }

        uint2 pk;
        pk.x = *(uint32_t*)&a01;
        pk.y = *(uint32_t*)&a23;
        *(uint2*)&g_feat[(size_t)gpt * D_ + lane * 4] = pk;
    }
}

// ---------------------------------------------------------------------------
// Kernel 3: MLP GEMM (fp16 mma) + epilogue (b1/relu/W2/tanh) + coord update.
// Block: 128 points. smem: Af [128][FSTR] fp16, W1h [128][FSTR] fp16.
// ---------------------------------------------------------------------------
#define FSTR 136
#define FEAT_ELEMS (128 * FSTR)
#define MLP_SMEM (2 * FEAT_ELEMS * 2)   // 69632 bytes

__global__ __launch_bounds__(256) void mlp_kernel(
    const float* __restrict__ coords, const float* __restrict__ W1,
    const float* __restrict__ b1,     const float* __restrict__ W2,
    const float* __restrict__ b2,     float* __restrict__ out)
{
    extern __shared__ __align__(16) __half smh[];
    __half* Af  = smh;                 // [128 pt][FSTR]
    __half* W1h = smh + FEAT_ELEMS;    // [128 j][FSTR]
    float*  red = (float*)smh;         // aliases Af after GEMM

    const int tid  = threadIdx.x;
    const int lane = tid & 31, warp = tid >> 5;
    const int ptBase = blockIdx.x * 128;

    // load feat tile (fp16 global, coalesced 16B)
    {
        const uint4* src = (const uint4*)(g_feat + (size_t)ptBase * D_);
#pragma unroll
        for (int i = 0; i < 8; i++) {
            int idx = i * 256 + tid;          // 2048 uint4 total
            int row = idx >> 4, c8 = (idx & 15) * 8;
            *(uint4*)&Af[row * FSTR + c8] = src[idx];
        }
    }
    // load W1 fp32 -> fp16 smem
    for (int i = tid; i < 128 * 128 / 4; i += 256) {
        int idx = i * 4;
        int j = idx >> 7, k = idx & 127;
        float4 v = *(const float4*)&W1[j * 128 + k];
        __half2* dst = (__half2*)&W1h[j * FSTR + k];
        dst[0] = __floats2half2_rn(v.x, v.y);
        dst[1] = __floats2half2_rn(v.z, v.w);
    }
    __syncthreads();

    const int wm = (warp & 3) * 32;
    const int wn = (warp >> 2) * 64;

    float acc[2][8][4];
#pragma unroll
    for (int mt = 0; mt < 2; mt++)
#pragma unroll
        for (int nt = 0; nt < 8; nt++)
#pragma unroll
            for (int q = 0; q < 4; q++) acc[mt][nt][q] = 0.f;

    const uint32_t abase = s2u(Af);
    const uint32_t bbase = s2u(W1h);

#pragma unroll
    for (int kc = 0; kc < 8; kc++) {
        int k0 = kc * 16;
        uint32_t af[2][4];
#pragma unroll
        for (int mt = 0; mt < 2; mt++) {
            int row = wm + mt * 16 + (lane & 15);
            int col = k0 + ((lane >> 4) << 3);
            ldm_x4(af[mt], abase + (row * FSTR + col) * 2);
        }
        uint32_t bf[8][2];
#pragma unroll
        for (int np = 0; np < 4; np++) {
            int n = wn + np * 16 + (lane & 7) + ((lane >> 4) << 3);
            int k = k0 + ((lane >> 3) & 1) * 8;
            uint32_t r[4];
            ldm_x4(r, bbase + (n * FSTR + k) * 2);
            bf[2 * np][0]     = r[0];  bf[2 * np][1]     = r[1];
            bf[2 * np + 1][0] = r[2];  bf[2 * np + 1][1] = r[3];
        }
#pragma unroll
        for (int mt = 0; mt < 2; mt++)
#pragma unroll
            for (int nt = 0; nt < 8; nt++)
                mma_f16(acc[mt][nt], af[mt], bf[nt]);
    }

    // epilogue: h = relu(acc + b1), partial W2 @ h
    float2 b1v[8], w20v[8], w21v[8];
#pragma unroll
    for (int nt = 0; nt < 8; nt++) {
        int j = wn + nt * 8 + (lane & 3) * 2;
        b1v[nt]  = *(const float2*)&b1[j];
        w20v[nt] = *(const float2*)&W2[j];
        w21v[nt] = *(const float2*)&W2[128 + j];
    }
    float s0[2][2], s1[2][2];
#pragma unroll
    for (int mt = 0; mt < 2; mt++)
#pragma unroll
        for (int hh = 0; hh < 2; hh++) { s0[mt][hh] = 0.f; s1[mt][hh] = 0.f; }
#pragma unroll
    for (int mt = 0; mt < 2; mt++)
#pragma unroll
        for (int nt = 0; nt < 8; nt++) {
            float h00 = fmaxf(acc[mt][nt][0] + b1v[nt].x, 0.f);
            float h01 = fmaxf(acc[mt][nt][1] + b1v[nt].y, 0.f);
            float h10 = fmaxf(acc[mt][nt][2] + b1v[nt].x, 0.f);
            float h11 = fmaxf(acc[mt][nt][3] + b1v[nt].y, 0.f);
            s0[mt][0] = fmaf(w20v[nt].x, h00, s0[mt][0]);
            s0[mt][0] = fmaf(w20v[nt].y, h01, s0[mt][0]);
            s1[mt][0] = fmaf(w21v[nt].x, h00, s1[mt][0]);
            s1[mt][0] = fmaf(w21v[nt].y, h01, s1[mt][0]);
            s0[mt][1] = fmaf(w20v[nt].x, h10, s0[mt][1]);
            s0[mt][1] = fmaf(w20v[nt].y, h11, s0[mt][1]);
            s1[mt][1] = fmaf(w21v[nt].x, h10, s1[mt][1]);
            s1[mt][1] = fmaf(w21v[nt].y, h11, s1[mt][1]);
        }

    __syncthreads();

    int p = (warp >> 2) * 4 + (lane & 3);
#pragma unroll
    for (int mt = 0; mt < 2; mt++)
#pragma unroll
        for (int hh = 0; hh < 2; hh++) {
            int row = wm + mt * 16 + (lane >> 2) + 8 * hh;
            red[(p * 128 + row) * 2 + 0] = s0[mt][hh];
            red[(p * 128 + row) * 2 + 1] = s1[mt][hh];
        }
    __syncthreads();

    {
        int pt = tid >> 1, c = tid & 1;
        float s = b2[c];
#pragma unroll
        for (int g = 0; g < 8; g++) s += red[(g * 128 + pt) * 2 + c];
        float v = tanhf(s) * MAX_DELTA;
        int gi = (ptBase + pt) * 2 + c;
        out[gi] = coords[gi] + v;
    }
}

// ---------------------------------------------------------------------------
extern "C" void kernel_launch(void* const* d_in, const int* in_sizes, int n_in,
                              void* d_out, int out_size)
{
    (void)in_sizes; (void)n_in; (void)out_size;
    const float* fmap   = (const float*)d_in[0];
    const float* coords = (const float*)d_in[1];
    const float* Wp     = (const float*)d_in[2];
    const float* W1     = (const float*)d_in[3];
    const float* b1     = (const float*)d_in[4];
    const float* W2     = (const float*)d_in[5];
    const float* b2     = (const float*)d_in[6];
    float* out = (float*)d_out;

    cudaFuncSetAttribute(proj_kernel,
                         cudaFuncAttributeMaxDynamicSharedMemorySize, PROJ_SMEM);
    proj_kernel<<<dim3(HW_ / 128, B_), 256, PROJ_SMEM>>>(fmap, Wp);

    sample_kernel<<<(B_ * T_) / 64, 256>>>(coords);

    cudaFuncSetAttribute(mlp_kernel,
                         cudaFuncAttributeMaxDynamicSharedMemorySize, MLP_SMEM);
    mlp_kernel<<<(B_ * T_) / 128, 256, MLP_SMEM>>>(coords, W1, b1, W2, b2, out);
}